// round 16
// baseline (speedup 1.0000x reference)
#include <cuda_runtime.h>
#include <cuda_fp16.h>
#include <cstdint>

#define EPSF 1e-5f
#define HW 3136                  // 56*56
#define M_TOT 100352             // 32*56*56
#define NTILES 25088             // 32*28*28  (2x2 output tiles)
#define KW_ELEM 589824           // 256*256*3*3

// e4m3 codes for quantized activation values {0,1,2,3} (byte_perm table)
#define ACT_E4M3 0x44403800u

// Output-transform coefficients per t=(a*4+b): {c00,c01,c10,c11}
// AT0 = {1,1,1,0}, AT1 = {0,1,-1,-1}
__device__ __constant__ float4 WCOEF[16] = {
    {1, 0, 0, 0}, {1, 1, 0, 0}, {1, -1, 0, 0}, {0, -1, 0, 0},
    {1, 0, 1, 0}, {1, 1, 1, 1}, {1, -1, 1, -1}, {0, -1, 0, -1},
    {1, 0, -1, 0}, {1, 1, -1, -1}, {1, -1, -1, 1}, {0, -1, 0, 1},
    {0, 0, -1, 0}, {0, 0, -1, -1}, {0, 0, -1, 1}, {0, 0, 0, 1}};

// ---------------- static device scratch ----------------
__device__ int g_maxbits[2];
__device__ __align__(128) __half g_U1[16 * 256 * 256];             // U[t][co][ci] fp16
__device__ __align__(128) __half g_U2[16 * 256 * 256];
__device__ __align__(128) uint8_t g_act0[(size_t)M_TOT * 256];     // NHWC e4m3, acts*3
__device__ __align__(128) uint8_t g_act1[(size_t)M_TOT * 256];
__device__ __align__(128) uint8_t g_V[(size_t)16 * NTILES * 256];  // V[t][tile][ci] e4m3 (ints |v|<=12)

__device__ __forceinline__ uint32_t smem_u32(const void* p) {
    uint32_t a;
    asm("{ .reg .u64 t; cvta.to.shared.u64 t, %1; cvt.u32.u64 %0, t; }" : "=r"(a) : "l"(p));
    return a;
}

__device__ __forceinline__ void ldsm_x4(uint32_t& f0, uint32_t& f1, uint32_t& f2,
                                        uint32_t& f3, uint32_t addr) {
    asm volatile("ldmatrix.sync.aligned.m8n8.x4.shared.b16 {%0,%1,%2,%3}, [%4];"
                 : "=r"(f0), "=r"(f1), "=r"(f2), "=r"(f3) : "r"(addr));
}

__device__ __forceinline__ void hmma16816(float* c, const uint32_t* a, uint32_t b0, uint32_t b1) {
    asm volatile(
        "mma.sync.aligned.m16n8k16.row.col.f32.f16.f16.f32 "
        "{%0,%1,%2,%3}, {%4,%5,%6,%7}, {%8,%9}, {%0,%1,%2,%3};"
        : "+f"(c[0]), "+f"(c[1]), "+f"(c[2]), "+f"(c[3])
        : "r"(a[0]), "r"(a[1]), "r"(a[2]), "r"(a[3]), "r"(b0), "r"(b1));
}

// e4m3x2 (low 16 bits) -> f16x2 ; exact for small integers
__device__ __forceinline__ uint32_t cvt_e4m3x2_f16x2(uint32_t v) {
    uint32_t r;
    asm("cvt.rn.f16x2.e4m3x2 %0, %1;" : "=r"(r) : "h"((uint16_t)v));
    return r;
}
// f16x2 -> e4m3x2 (low 16 bits) ; exact for ints |v|<=16
__device__ __forceinline__ uint32_t cvt_f16x2_e4m3x2(__half2 h) {
    uint16_t r;
    asm("cvt.rn.satfinite.e4m3x2.f16x2 %0, %1;"
        : "=h"(r) : "r"(*reinterpret_cast<uint32_t*>(&h)));
    return (uint32_t)r;
}

// ---------------- prep kernels ----------------
__global__ void init_kernel() {
    g_maxbits[0] = 0;
    g_maxbits[1] = 0;
}

__global__ void wmax_kernel(const float* __restrict__ w1, const float* __restrict__ w2) {
    const float* w = blockIdx.y ? w2 : w1;
    float mx = 0.f;
    for (int i = blockIdx.x * blockDim.x + threadIdx.x; i < KW_ELEM;
         i += gridDim.x * blockDim.x)
        mx = fmaxf(mx, fabsf(tanhf(w[i])));
#pragma unroll
    for (int o = 16; o; o >>= 1)
        mx = fmaxf(mx, __shfl_xor_sync(0xffffffffu, mx, o));
    if ((threadIdx.x & 31) == 0)
        atomicMax(&g_maxbits[blockIdx.y], __float_as_int(mx));
}

// DoReFa weight quant (*3) fused with Winograd weight transform U = G w G^T (fp16, exact)
__global__ void utrans_kernel(const float* __restrict__ w1, const float* __restrict__ w2) {
    __shared__ float ws[2304];
    int which = blockIdx.y;
    const float* w = which ? w2 : w1;
    __half* U = which ? g_U2 : g_U1;
    int co = blockIdx.x, t = threadIdx.x;
    for (int i = t; i < 2304; i += 256) ws[i] = w[(size_t)co * 2304 + i];
    __syncthreads();
    float s = 1.f / (2.f * __int_as_float(g_maxbits[which]));
    float g[3][3];
#pragma unroll
    for (int i = 0; i < 3; i++)
#pragma unroll
        for (int j = 0; j < 3; j++) {
            float q = rintf((tanhf(ws[t * 9 + i * 3 + j]) * s + 0.5f) * 3.f);
            g[i][j] = 2.f * q - 3.f;                 // {-3,-1,1,3}
        }
    float r[4][3];
#pragma unroll
    for (int j = 0; j < 3; j++) {
        r[0][j] = g[0][j];
        r[1][j] = 0.5f * (g[0][j] + g[1][j] + g[2][j]);
        r[2][j] = 0.5f * (g[0][j] - g[1][j] + g[2][j]);
        r[3][j] = g[2][j];
    }
#pragma unroll
    for (int a = 0; a < 4; a++) {
        float u0 = r[a][0];
        float u1 = 0.5f * (r[a][0] + r[a][1] + r[a][2]);
        float u2 = 0.5f * (r[a][0] - r[a][1] + r[a][2]);
        float u3 = r[a][2];
        size_t base = ((size_t)(a * 4) * 256 + co) * 256 + t;
        size_t tstr = (size_t)256 * 256;
        U[base + 0 * tstr] = __float2half_rn(u0);
        U[base + 1 * tstr] = __float2half_rn(u1);
        U[base + 2 * tstr] = __float2half_rn(u2);
        U[base + 3 * tstr] = __float2half_rn(u3);
    }
}

// BN1 + ReLU + 2-bit quant (*3) + NCHW -> NHWC e4m3
__global__ void actprep_kernel(const float* __restrict__ x,
                               const float* __restrict__ g1, const float* __restrict__ b1,
                               const float* __restrict__ m1, const float* __restrict__ v1) {
    __shared__ float ivs[256], bis[256];
    __shared__ __align__(16) uint8_t tile[56 * 260];
    int t = threadIdx.x;
    if (t < 256) {
        float iv = g1[t] / sqrtf(v1[t] + EPSF);
        ivs[t] = iv;
        bis[t] = b1[t] - m1[t] * iv;
    }
    __syncthreads();
    int nb = blockIdx.x;
    int n = nb / 56, y = nb % 56;
    const float* xr = x + (size_t)n * 256 * HW + y * 56;
    for (int idx = t; idx < 256 * 56; idx += blockDim.x) {
        int c = idx / 56, xx = idx % 56;
        float h = xr[(size_t)c * HW + xx] * ivs[c] + bis[c];
        h = fminf(fmaxf(h, 0.f), 1.f);
        int q = (int)rintf(h * 3.f);
        tile[xx * 260 + c] = (uint8_t)__byte_perm(ACT_E4M3, 0, q);
    }
    __syncthreads();
    uint32_t* o = (uint32_t*)(g_act0 + (size_t)((n * 56 + y) * 56) * 256);
    for (int idx = t; idx < 56 * 64; idx += blockDim.x) {
        int xx = idx >> 6, cq = idx & 63;
        o[xx * 64 + cq] = *(const uint32_t*)&tile[xx * 260 + cq * 4];
    }
}

// ---------------- Winograd input transform: act(e4m3) -> V(e4m3) ----------------
// block 256 threads: 4 tiles/block, 64 threads/tile, 4 ci each. grid = NTILES/4
__global__ void vtrans_kernel(int which) {
    const uint8_t* act = which ? g_act1 : g_act0;
    int tid = threadIdx.x;
    int tile = blockIdx.x * 4 + (tid >> 6);
    int cp = tid & 63;                        // 4-ci group
    int n = tile / 784;
    int r = tile - n * 784;
    int ty = r / 28, tx = r - (r / 28) * 28;
    const uint32_t* ap = (const uint32_t*)act + cp;
    int y0 = 2 * ty - 1, x0 = 2 * tx - 1;
    __half2 dl[4][4], dh[4][4];
#pragma unroll
    for (int p = 0; p < 4; p++) {
        int y = y0 + p;
        bool yv = (y >= 0) && (y < 56);
#pragma unroll
        for (int q = 0; q < 4; q++) {
            int x = x0 + q;
            uint32_t v = 0;
            if (yv && x >= 0 && x < 56)
                v = ap[(size_t)((n * 56 + y) * 56 + x) * 64];
            uint32_t lo = cvt_e4m3x2_f16x2(v & 0xFFFFu);
            uint32_t hi = cvt_e4m3x2_f16x2(v >> 16);
            dl[p][q] = *reinterpret_cast<__half2*>(&lo);
            dh[p][q] = *reinterpret_cast<__half2*>(&hi);
        }
    }
    __half2 el[4][4], eh[4][4];
#pragma unroll
    for (int q = 0; q < 4; q++) {
        el[0][q] = __hsub2(dl[0][q], dl[2][q]);
        el[1][q] = __hadd2(dl[1][q], dl[2][q]);
        el[2][q] = __hsub2(dl[2][q], dl[1][q]);
        el[3][q] = __hsub2(dl[1][q], dl[3][q]);
        eh[0][q] = __hsub2(dh[0][q], dh[2][q]);
        eh[1][q] = __hadd2(dh[1][q], dh[2][q]);
        eh[2][q] = __hsub2(dh[2][q], dh[1][q]);
        eh[3][q] = __hsub2(dh[1][q], dh[3][q]);
    }
    uint32_t* vp = (uint32_t*)g_V + (size_t)tile * 64 + cp;
    const size_t tstr = (size_t)NTILES * 64;
#pragma unroll
    for (int a = 0; a < 4; a++) {
        __half2 l0 = __hsub2(el[a][0], el[a][2]);
        __half2 l1 = __hadd2(el[a][1], el[a][2]);
        __half2 l2 = __hsub2(el[a][2], el[a][1]);
        __half2 l3 = __hsub2(el[a][1], el[a][3]);
        __half2 h0 = __hsub2(eh[a][0], eh[a][2]);
        __half2 h1 = __hadd2(eh[a][1], eh[a][2]);
        __half2 h2 = __hsub2(eh[a][2], eh[a][1]);
        __half2 h3 = __hsub2(eh[a][1], eh[a][3]);
        vp[(size_t)(a * 4 + 0) * tstr] = cvt_f16x2_e4m3x2(l0) | (cvt_f16x2_e4m3x2(h0) << 16);
        vp[(size_t)(a * 4 + 1) * tstr] = cvt_f16x2_e4m3x2(l1) | (cvt_f16x2_e4m3x2(h1) << 16);
        vp[(size_t)(a * 4 + 2) * tstr] = cvt_f16x2_e4m3x2(l2) | (cvt_f16x2_e4m3x2(h2) << 16);
        vp[(size_t)(a * 4 + 3) * tstr] = cvt_f16x2_e4m3x2(l3) | (cvt_f16x2_e4m3x2(h3) << 16);
    }
}

// ---------------- Winograd batched GEMM (fp16 HMMA) + fused output transform ----------------
// CTA: 64 tiles x 64 co, 256 threads (8 warps, grid 4x392 -> occupancy 2).
// 64 double-buffered 64-ci stages; A e4m3->f16 in regs; B LDG/STS.
// Software pipeline: COMP(s) -> STS(s+1) -> LDG(s+2) -> bar, so global latency is hidden
// across barrier+COMP instead of stalling STS.
#define A_STRIDE 144
#define A_BUFSZ 9216            // 64*144
#define B_BASE_OFF 18432
#define B_BUFSZ 9216            // 64*144
#define IVS_OFF 36864
#define BIS_OFF 37888
#define WG_SMEM 38912

__global__ __launch_bounds__(256, 2)
void wgemm_kernel(int phase,
                  const float* __restrict__ g2, const float* __restrict__ b2,
                  const float* __restrict__ m2, const float* __restrict__ v2,
                  const float* __restrict__ xin, float* __restrict__ out) {
    extern __shared__ __align__(128) uint8_t smem[];
    float* ivs = (float*)(smem + IVS_OFF);
    float* bis = (float*)(smem + BIS_OFF);
    const uint32_t sbase = smem_u32(smem);

    const uint8_t* __restrict__ Vb = g_V;
    const uint8_t* __restrict__ Ub = (const uint8_t*)(phase == 1 ? g_U1 : g_U2);

    const int t = threadIdx.x;
    const int wid = t >> 5, lid = t & 31;
    const int wm = wid & 3, wn = wid >> 2;        // 4(M) x 2(N) warp grid
    const int g = lid >> 2, tig = lid & 3;

    const int cob = blockIdx.x * 64;              // co split first -> V-sharing CTAs adjacent
    const int tileb = blockIdx.y * 64;

    if (phase == 1) {
        float iv = g2[t] / sqrtf(v2[t] + EPSF);
        ivs[t] = iv;
        bis[t] = b2[t] - m2[t] * iv;
    }

    // loaders: A 64 rows x 4 segs(16B e4m3 -> 32B fp16); B 64 rows x 4 segs(32B fp16)
    const int arow = t >> 2, aseg = t & 3;
    const int brow = t >> 2, bcol = (t & 3) * 32;

    uint4 la8;
    int4 lb0, lb1;
    auto LDG = [&](int s) {
        int tt = s >> 2, kc = s & 3;
        la8 = *(const uint4*)(Vb + ((size_t)tt * NTILES + tileb + arow) * 256 +
                              kc * 64 + aseg * 16);
        const uint8_t* bp = Ub + ((size_t)tt * 256 + cob + brow) * 512 + kc * 128 + bcol;
        lb0 = ((const int4*)bp)[0];
        lb1 = ((const int4*)bp)[1];
    };
    auto STS = [&](int buf) {
        int4 lo, hi;
        lo.x = (int)cvt_e4m3x2_f16x2(la8.x & 0xFFFFu);
        lo.y = (int)cvt_e4m3x2_f16x2(la8.x >> 16);
        lo.z = (int)cvt_e4m3x2_f16x2(la8.y & 0xFFFFu);
        lo.w = (int)cvt_e4m3x2_f16x2(la8.y >> 16);
        hi.x = (int)cvt_e4m3x2_f16x2(la8.z & 0xFFFFu);
        hi.y = (int)cvt_e4m3x2_f16x2(la8.z >> 16);
        hi.z = (int)cvt_e4m3x2_f16x2(la8.w & 0xFFFFu);
        hi.w = (int)cvt_e4m3x2_f16x2(la8.w >> 16);
        uint8_t* ad = smem + buf * A_BUFSZ + arow * A_STRIDE + aseg * 32;
        ((int4*)ad)[0] = lo;
        ((int4*)ad)[1] = hi;
        uint8_t* q = smem + B_BASE_OFF + buf * B_BUFSZ + brow * A_STRIDE + bcol;
        ((int4*)q)[0] = lb0;
        ((int4*)q)[1] = lb1;
    };

    const uint32_t aoff = (uint32_t)((wm * 16 + (lid & 15)) * A_STRIDE + (lid >> 4) * 16);
    uint32_t boff[2];
#pragma unroll
    for (int j = 0; j < 2; j++)
        boff[j] = (uint32_t)((wn * 32 + j * 16 + (lid & 7) + ((lid >> 4) & 1) * 8) * A_STRIDE +
                             ((lid >> 3) & 1) * 16);

    float fr[4][4];
#pragma unroll
    for (int n = 0; n < 4; n++)
#pragma unroll
        for (int c = 0; c < 4; c++) fr[n][c] = 0.f;

    float O_[2][4][2][4];
#pragma unroll
    for (int a = 0; a < 2; a++)
#pragma unroll
        for (int b = 0; b < 4; b++)
#pragma unroll
            for (int c = 0; c < 2; c++)
#pragma unroll
                for (int d = 0; d < 4; d++) O_[a][b][c][d] = 0.f;

    auto COMP = [&](int buf) {
        uint32_t ab = sbase + buf * A_BUFSZ;
        uint32_t bb = sbase + B_BASE_OFF + buf * B_BUFSZ;
#pragma unroll
        for (int ks = 0; ks < 4; ks++) {
            uint32_t A[4];
            ldsm_x4(A[0], A[1], A[2], A[3], ab + aoff + ks * 32);
#pragma unroll
            for (int j = 0; j < 2; j++) {
                uint32_t b0, b1, b2_, b3;
                ldsm_x4(b0, b1, b2_, b3, bb + boff[j] + ks * 32);
                hmma16816(fr[j * 2 + 0], A, b0, b1);
                hmma16816(fr[j * 2 + 1], A, b2_, b3);
            }
        }
    };

    // prologue: fill buffer 0, stage load for buffer 1
    LDG(0);
    STS(0);
    LDG(1);
    __syncthreads();
#pragma unroll 1
    for (int s = 0; s < 64; s++) {
        COMP(s & 1);
        if ((s & 3) == 3) {
            float4 cc = WCOEF[s >> 2];
#pragma unroll
            for (int nf = 0; nf < 4; nf++)
#pragma unroll
                for (int ti = 0; ti < 2; ti++)
#pragma unroll
                    for (int cci = 0; cci < 2; cci++) {
                        float m = fr[nf][ti * 2 + cci];
                        O_[ti][nf][cci][0] += cc.x * m;
                        O_[ti][nf][cci][1] += cc.y * m;
                        O_[ti][nf][cci][2] += cc.z * m;
                        O_[ti][nf][cci][3] += cc.w * m;
                    }
#pragma unroll
            for (int n = 0; n < 4; n++)
#pragma unroll
                for (int c = 0; c < 4; c++) fr[n][c] = 0.f;
        }
        if (s < 63) {
            STS((s + 1) & 1);      // staged regs from LDG(s+1), loaded one iteration back
            if (s < 62) LDG(s + 2);
        }
        __syncthreads();
    }

    // ---------------- epilogue (fragment-direct stores) ----------------
#pragma unroll
    for (int ti = 0; ti < 2; ti++) {
        int tglob = tileb + wm * 16 + g + ti * 8;
        int n = tglob / 784;
        int r = tglob - n * 784;
        int ty = r / 28, tx = r - (r / 28) * 28;
        int y0 = 2 * ty, x0 = 2 * tx;

        if (phase == 1) {
#pragma unroll
            for (int py = 0; py < 2; py++)
#pragma unroll
                for (int px = 0; px < 2; px++) {
                    size_t pix = (size_t)((n * 56 + y0 + py) * 56 + x0 + px) * 256;
#pragma unroll
                    for (int nf = 0; nf < 4; nf++) {
                        int c = cob + wn * 32 + nf * 8 + tig * 2;
                        float v0 = O_[ti][nf][0][py * 2 + px] * (1.f / 9.f) * ivs[c] + bis[c];
                        float v1 = O_[ti][nf][1][py * 2 + px] * (1.f / 9.f) * ivs[c + 1] + bis[c + 1];
                        v0 = fminf(fmaxf(v0, 0.f), 1.f);
                        v1 = fminf(fmaxf(v1, 0.f), 1.f);
                        int q0 = (int)rintf(v0 * 3.f);
                        int q1 = (int)rintf(v1 * 3.f);
                        uchar2 pk;
                        pk.x = (uint8_t)__byte_perm(ACT_E4M3, 0, q0);
                        pk.y = (uint8_t)__byte_perm(ACT_E4M3, 0, q1);
                        *(uchar2*)(g_act1 + pix + c) = pk;
                    }
                }
        } else {
#pragma unroll
            for (int nf = 0; nf < 4; nf++)
#pragma unroll
                for (int cci = 0; cci < 2; cci++) {
                    int c = cob + wn * 32 + nf * 8 + tig * 2 + cci;
                    size_t base = ((size_t)n * 256 + c) * HW;
#pragma unroll
                    for (int py = 0; py < 2; py++) {
                        size_t idx = base + (size_t)(y0 + py) * 56 + x0;
                        out[idx] = O_[ti][nf][cci][py * 2 + 0] * (1.f / 9.f) + xin[idx];
                        out[idx + 1] = O_[ti][nf][cci][py * 2 + 1] * (1.f / 9.f) + xin[idx + 1];
                    }
                }
        }
    }
}

// ---------------- launch ----------------
extern "C" void kernel_launch(void* const* d_in, const int* in_sizes, int n_in,
                              void* d_out, int out_size) {
    const float* x  = (const float*)d_in[0];
    const float* w1 = (const float*)d_in[1];
    const float* w2 = (const float*)d_in[2];
    const float* g1 = (const float*)d_in[3];
    const float* b1 = (const float*)d_in[4];
    const float* m1 = (const float*)d_in[5];
    const float* v1 = (const float*)d_in[6];
    const float* g2 = (const float*)d_in[7];
    const float* b2 = (const float*)d_in[8];
    const float* m2 = (const float*)d_in[9];
    const float* v2 = (const float*)d_in[10];
    float* out = (float*)d_out;
    (void)in_sizes; (void)n_in; (void)out_size;

    cudaFuncSetAttribute(wgemm_kernel,
                         cudaFuncAttributeMaxDynamicSharedMemorySize, WG_SMEM);

    init_kernel<<<1, 1>>>();
    wmax_kernel<<<dim3(128, 2), 256>>>(w1, w2);
    utrans_kernel<<<dim3(256, 2), 256>>>(w1, w2);
    actprep_kernel<<<32 * 56, 256>>>(x, g1, b1, m1, v1);
    vtrans_kernel<<<NTILES / 4, 256>>>(0);
    wgemm_kernel<<<dim3(4, 392), 256, WG_SMEM>>>(1, g2, b2, m2, v2, x, out);
    vtrans_kernel<<<NTILES / 4, 256>>>(1);
    wgemm_kernel<<<dim3(4, 392), 256, WG_SMEM>>>(2, g2, b2, m2, v2, x, out);
}

// round 17
// speedup vs baseline: 1.0263x; 1.0263x over previous
#include <cuda_runtime.h>
#include <cuda_fp16.h>
#include <cstdint>

#define EPSF 1e-5f
#define HW 3136                  // 56*56
#define M_TOT 100352             // 32*56*56
#define NTILES 25088             // 32*28*28  (2x2 output tiles)
#define KW_ELEM 589824           // 256*256*3*3

// e4m3 codes for quantized activation values {0,1,2,3} (byte_perm table)
#define ACT_E4M3 0x44403800u

// Output-transform coefficients per t=(a*4+b): {c00,c01,c10,c11}
// AT0 = {1,1,1,0}, AT1 = {0,1,-1,-1}
__device__ __constant__ float4 WCOEF[16] = {
    {1, 0, 0, 0}, {1, 1, 0, 0}, {1, -1, 0, 0}, {0, -1, 0, 0},
    {1, 0, 1, 0}, {1, 1, 1, 1}, {1, -1, 1, -1}, {0, -1, 0, -1},
    {1, 0, -1, 0}, {1, 1, -1, -1}, {1, -1, -1, 1}, {0, -1, 0, 1},
    {0, 0, -1, 0}, {0, 0, -1, -1}, {0, 0, -1, 1}, {0, 0, 0, 1}};

// ---------------- static device scratch ----------------
__device__ int g_maxbits[2];
__device__ __align__(128) __half g_U1[16 * 256 * 256];             // U[t][co][ci] fp16
__device__ __align__(128) __half g_U2[16 * 256 * 256];
__device__ __align__(128) uint8_t g_act0[(size_t)M_TOT * 256];     // NHWC e4m3, acts*3
__device__ __align__(128) uint8_t g_act1[(size_t)M_TOT * 256];
__device__ __align__(128) uint8_t g_V[(size_t)16 * NTILES * 256];  // V[t][tile][ci] e4m3 (ints |v|<=12)

__device__ __forceinline__ uint32_t smem_u32(const void* p) {
    uint32_t a;
    asm("{ .reg .u64 t; cvta.to.shared.u64 t, %1; cvt.u32.u64 %0, t; }" : "=r"(a) : "l"(p));
    return a;
}

__device__ __forceinline__ void ldsm_x4(uint32_t& f0, uint32_t& f1, uint32_t& f2,
                                        uint32_t& f3, uint32_t addr) {
    asm volatile("ldmatrix.sync.aligned.m8n8.x4.shared.b16 {%0,%1,%2,%3}, [%4];"
                 : "=r"(f0), "=r"(f1), "=r"(f2), "=r"(f3) : "r"(addr));
}

__device__ __forceinline__ void hmma16816(float* c, const uint32_t* a, uint32_t b0, uint32_t b1) {
    asm volatile(
        "mma.sync.aligned.m16n8k16.row.col.f32.f16.f16.f32 "
        "{%0,%1,%2,%3}, {%4,%5,%6,%7}, {%8,%9}, {%0,%1,%2,%3};"
        : "+f"(c[0]), "+f"(c[1]), "+f"(c[2]), "+f"(c[3])
        : "r"(a[0]), "r"(a[1]), "r"(a[2]), "r"(a[3]), "r"(b0), "r"(b1));
}

// e4m3x2 (low 16 bits) -> f16x2 ; exact for small integers
__device__ __forceinline__ uint32_t cvt_e4m3x2_f16x2(uint32_t v) {
    uint32_t r;
    asm("cvt.rn.f16x2.e4m3x2 %0, %1;" : "=r"(r) : "h"((uint16_t)v));
    return r;
}
// f16x2 -> e4m3x2 (low 16 bits) ; exact for ints |v|<=16
__device__ __forceinline__ uint32_t cvt_f16x2_e4m3x2(__half2 h) {
    uint16_t r;
    asm("cvt.rn.satfinite.e4m3x2.f16x2 %0, %1;"
        : "=h"(r) : "r"(*reinterpret_cast<uint32_t*>(&h)));
    return (uint32_t)r;
}

// ---------------- prep kernels ----------------
__global__ void init_kernel() {
    g_maxbits[0] = 0;
    g_maxbits[1] = 0;
}

__global__ void wmax_kernel(const float* __restrict__ w1, const float* __restrict__ w2) {
    const float* w = blockIdx.y ? w2 : w1;
    float mx = 0.f;
    for (int i = blockIdx.x * blockDim.x + threadIdx.x; i < KW_ELEM;
         i += gridDim.x * blockDim.x)
        mx = fmaxf(mx, fabsf(tanhf(w[i])));
#pragma unroll
    for (int o = 16; o; o >>= 1)
        mx = fmaxf(mx, __shfl_xor_sync(0xffffffffu, mx, o));
    if ((threadIdx.x & 31) == 0)
        atomicMax(&g_maxbits[blockIdx.y], __float_as_int(mx));
}

// DoReFa weight quant (*3) fused with Winograd weight transform U = G w G^T (fp16, exact)
__global__ void utrans_kernel(const float* __restrict__ w1, const float* __restrict__ w2) {
    __shared__ float ws[2304];
    int which = blockIdx.y;
    const float* w = which ? w2 : w1;
    __half* U = which ? g_U2 : g_U1;
    int co = blockIdx.x, t = threadIdx.x;
    for (int i = t; i < 2304; i += 256) ws[i] = w[(size_t)co * 2304 + i];
    __syncthreads();
    float s = 1.f / (2.f * __int_as_float(g_maxbits[which]));
    float g[3][3];
#pragma unroll
    for (int i = 0; i < 3; i++)
#pragma unroll
        for (int j = 0; j < 3; j++) {
            float q = rintf((tanhf(ws[t * 9 + i * 3 + j]) * s + 0.5f) * 3.f);
            g[i][j] = 2.f * q - 3.f;                 // {-3,-1,1,3}
        }
    float r[4][3];
#pragma unroll
    for (int j = 0; j < 3; j++) {
        r[0][j] = g[0][j];
        r[1][j] = 0.5f * (g[0][j] + g[1][j] + g[2][j]);
        r[2][j] = 0.5f * (g[0][j] - g[1][j] + g[2][j]);
        r[3][j] = g[2][j];
    }
#pragma unroll
    for (int a = 0; a < 4; a++) {
        float u0 = r[a][0];
        float u1 = 0.5f * (r[a][0] + r[a][1] + r[a][2]);
        float u2 = 0.5f * (r[a][0] - r[a][1] + r[a][2]);
        float u3 = r[a][2];
        size_t base = ((size_t)(a * 4) * 256 + co) * 256 + t;
        size_t tstr = (size_t)256 * 256;
        U[base + 0 * tstr] = __float2half_rn(u0);
        U[base + 1 * tstr] = __float2half_rn(u1);
        U[base + 2 * tstr] = __float2half_rn(u2);
        U[base + 3 * tstr] = __float2half_rn(u3);
    }
}

// BN1 + ReLU + 2-bit quant (*3) + NCHW -> NHWC e4m3 (float2 loads: half the iters, 2x MLP)
__global__ void actprep_kernel(const float* __restrict__ x,
                               const float* __restrict__ g1, const float* __restrict__ b1,
                               const float* __restrict__ m1, const float* __restrict__ v1) {
    __shared__ float ivs[256], bis[256];
    __shared__ __align__(16) uint8_t tile[56 * 260];
    int t = threadIdx.x;
    if (t < 256) {
        float iv = g1[t] / sqrtf(v1[t] + EPSF);
        ivs[t] = iv;
        bis[t] = b1[t] - m1[t] * iv;
    }
    __syncthreads();
    int nb = blockIdx.x;
    int n = nb / 56, y = nb % 56;
    const float* xr = x + (size_t)n * 256 * HW + y * 56;
    for (int idx = t; idx < 256 * 28; idx += blockDim.x) {
        int c = idx / 28, x2 = idx - (idx / 28) * 28;
        float2 v = *(const float2*)(xr + (size_t)c * HW + x2 * 2);
        float iv = ivs[c], bi = bis[c];
        float h0 = fminf(fmaxf(v.x * iv + bi, 0.f), 1.f);
        float h1 = fminf(fmaxf(v.y * iv + bi, 0.f), 1.f);
        int q0 = (int)rintf(h0 * 3.f);
        int q1 = (int)rintf(h1 * 3.f);
        tile[(x2 * 2 + 0) * 260 + c] = (uint8_t)__byte_perm(ACT_E4M3, 0, q0);
        tile[(x2 * 2 + 1) * 260 + c] = (uint8_t)__byte_perm(ACT_E4M3, 0, q1);
    }
    __syncthreads();
    uint32_t* o = (uint32_t*)(g_act0 + (size_t)((n * 56 + y) * 56) * 256);
    for (int idx = t; idx < 56 * 64; idx += blockDim.x) {
        int xx = idx >> 6, cq = idx & 63;
        o[xx * 64 + cq] = *(const uint32_t*)&tile[xx * 260 + cq * 4];
    }
}

// ---------------- Winograd input transform: act(e4m3) -> V(e4m3) ----------------
// block 256 threads: 4 tiles/block, 64 threads/tile, 4 ci each. grid = NTILES/4
__global__ void vtrans_kernel(int which) {
    const uint8_t* act = which ? g_act1 : g_act0;
    int tid = threadIdx.x;
    int tile = blockIdx.x * 4 + (tid >> 6);
    int cp = tid & 63;                        // 4-ci group
    int n = tile / 784;
    int r = tile - n * 784;
    int ty = r / 28, tx = r - (r / 28) * 28;
    const uint32_t* ap = (const uint32_t*)act + cp;
    int y0 = 2 * ty - 1, x0 = 2 * tx - 1;
    __half2 dl[4][4], dh[4][4];
#pragma unroll
    for (int p = 0; p < 4; p++) {
        int y = y0 + p;
        bool yv = (y >= 0) && (y < 56);
#pragma unroll
        for (int q = 0; q < 4; q++) {
            int x = x0 + q;
            uint32_t v = 0;
            if (yv && x >= 0 && x < 56)
                v = ap[(size_t)((n * 56 + y) * 56 + x) * 64];
            uint32_t lo = cvt_e4m3x2_f16x2(v & 0xFFFFu);
            uint32_t hi = cvt_e4m3x2_f16x2(v >> 16);
            dl[p][q] = *reinterpret_cast<__half2*>(&lo);
            dh[p][q] = *reinterpret_cast<__half2*>(&hi);
        }
    }
    __half2 el[4][4], eh[4][4];
#pragma unroll
    for (int q = 0; q < 4; q++) {
        el[0][q] = __hsub2(dl[0][q], dl[2][q]);
        el[1][q] = __hadd2(dl[1][q], dl[2][q]);
        el[2][q] = __hsub2(dl[2][q], dl[1][q]);
        el[3][q] = __hsub2(dl[1][q], dl[3][q]);
        eh[0][q] = __hsub2(dh[0][q], dh[2][q]);
        eh[1][q] = __hadd2(dh[1][q], dh[2][q]);
        eh[2][q] = __hsub2(dh[2][q], dh[1][q]);
        eh[3][q] = __hsub2(dh[1][q], dh[3][q]);
    }
    uint32_t* vp = (uint32_t*)g_V + (size_t)tile * 64 + cp;
    const size_t tstr = (size_t)NTILES * 64;
#pragma unroll
    for (int a = 0; a < 4; a++) {
        __half2 l0 = __hsub2(el[a][0], el[a][2]);
        __half2 l1 = __hadd2(el[a][1], el[a][2]);
        __half2 l2 = __hsub2(el[a][2], el[a][1]);
        __half2 l3 = __hsub2(el[a][1], el[a][3]);
        __half2 h0 = __hsub2(eh[a][0], eh[a][2]);
        __half2 h1 = __hadd2(eh[a][1], eh[a][2]);
        __half2 h2 = __hsub2(eh[a][2], eh[a][1]);
        __half2 h3 = __hsub2(eh[a][1], eh[a][3]);
        vp[(size_t)(a * 4 + 0) * tstr] = cvt_f16x2_e4m3x2(l0) | (cvt_f16x2_e4m3x2(h0) << 16);
        vp[(size_t)(a * 4 + 1) * tstr] = cvt_f16x2_e4m3x2(l1) | (cvt_f16x2_e4m3x2(h1) << 16);
        vp[(size_t)(a * 4 + 2) * tstr] = cvt_f16x2_e4m3x2(l2) | (cvt_f16x2_e4m3x2(h2) << 16);
        vp[(size_t)(a * 4 + 3) * tstr] = cvt_f16x2_e4m3x2(l3) | (cvt_f16x2_e4m3x2(h3) << 16);
    }
}

// ---------------- Winograd batched GEMM (fp16 HMMA) + fused output transform ----------------
// CTA: 64 tiles x 64 co, 256 threads (8 warps, grid 4x392 -> occupancy 2).
// 64 double-buffered 64-ci stages; A e4m3->f16 in regs; B LDG/STS.
// Round-15 proven stage order: LDG(s+1) -> COMP(s) -> STS(s+1) -> bar.
#define A_STRIDE 144
#define A_BUFSZ 9216            // 64*144
#define B_BASE_OFF 18432
#define B_BUFSZ 9216            // 64*144
#define IVS_OFF 36864
#define BIS_OFF 37888
#define WG_SMEM 38912

__global__ __launch_bounds__(256, 2)
void wgemm_kernel(int phase,
                  const float* __restrict__ g2, const float* __restrict__ b2,
                  const float* __restrict__ m2, const float* __restrict__ v2,
                  const float* __restrict__ xin, float* __restrict__ out) {
    extern __shared__ __align__(128) uint8_t smem[];
    float* ivs = (float*)(smem + IVS_OFF);
    float* bis = (float*)(smem + BIS_OFF);
    const uint32_t sbase = smem_u32(smem);

    const uint8_t* __restrict__ Vb = g_V;
    const uint8_t* __restrict__ Ub = (const uint8_t*)(phase == 1 ? g_U1 : g_U2);

    const int t = threadIdx.x;
    const int wid = t >> 5, lid = t & 31;
    const int wm = wid & 3, wn = wid >> 2;        // 4(M) x 2(N) warp grid
    const int g = lid >> 2, tig = lid & 3;

    const int cob = blockIdx.x * 64;              // co split first -> V-sharing CTAs adjacent
    const int tileb = blockIdx.y * 64;

    if (phase == 1) {
        float iv = g2[t] / sqrtf(v2[t] + EPSF);
        ivs[t] = iv;
        bis[t] = b2[t] - m2[t] * iv;
    }

    // loaders: A 64 rows x 4 segs(16B e4m3 -> 32B fp16); B 64 rows x 4 segs(32B fp16)
    const int arow = t >> 2, aseg = t & 3;
    const int brow = t >> 2, bcol = (t & 3) * 32;

    uint4 la8;
    int4 lb0, lb1;
    auto LDG = [&](int s) {
        int tt = s >> 2, kc = s & 3;
        la8 = *(const uint4*)(Vb + ((size_t)tt * NTILES + tileb + arow) * 256 +
                              kc * 64 + aseg * 16);
        const uint8_t* bp = Ub + ((size_t)tt * 256 + cob + brow) * 512 + kc * 128 + bcol;
        lb0 = ((const int4*)bp)[0];
        lb1 = ((const int4*)bp)[1];
    };
    auto STS = [&](int buf) {
        int4 lo, hi;
        lo.x = (int)cvt_e4m3x2_f16x2(la8.x & 0xFFFFu);
        lo.y = (int)cvt_e4m3x2_f16x2(la8.x >> 16);
        lo.z = (int)cvt_e4m3x2_f16x2(la8.y & 0xFFFFu);
        lo.w = (int)cvt_e4m3x2_f16x2(la8.y >> 16);
        hi.x = (int)cvt_e4m3x2_f16x2(la8.z & 0xFFFFu);
        hi.y = (int)cvt_e4m3x2_f16x2(la8.z >> 16);
        hi.z = (int)cvt_e4m3x2_f16x2(la8.w & 0xFFFFu);
        hi.w = (int)cvt_e4m3x2_f16x2(la8.w >> 16);
        uint8_t* ad = smem + buf * A_BUFSZ + arow * A_STRIDE + aseg * 32;
        ((int4*)ad)[0] = lo;
        ((int4*)ad)[1] = hi;
        uint8_t* q = smem + B_BASE_OFF + buf * B_BUFSZ + brow * A_STRIDE + bcol;
        ((int4*)q)[0] = lb0;
        ((int4*)q)[1] = lb1;
    };

    const uint32_t aoff = (uint32_t)((wm * 16 + (lid & 15)) * A_STRIDE + (lid >> 4) * 16);
    uint32_t boff[2];
#pragma unroll
    for (int j = 0; j < 2; j++)
        boff[j] = (uint32_t)((wn * 32 + j * 16 + (lid & 7) + ((lid >> 4) & 1) * 8) * A_STRIDE +
                             ((lid >> 3) & 1) * 16);

    float fr[4][4];
#pragma unroll
    for (int n = 0; n < 4; n++)
#pragma unroll
        for (int c = 0; c < 4; c++) fr[n][c] = 0.f;

    float O_[2][4][2][4];
#pragma unroll
    for (int a = 0; a < 2; a++)
#pragma unroll
        for (int b = 0; b < 4; b++)
#pragma unroll
            for (int c = 0; c < 2; c++)
#pragma unroll
                for (int d = 0; d < 4; d++) O_[a][b][c][d] = 0.f;

    auto COMP = [&](int buf) {
        uint32_t ab = sbase + buf * A_BUFSZ;
        uint32_t bb = sbase + B_BASE_OFF + buf * B_BUFSZ;
#pragma unroll
        for (int ks = 0; ks < 4; ks++) {
            uint32_t A[4];
            ldsm_x4(A[0], A[1], A[2], A[3], ab + aoff + ks * 32);
#pragma unroll
            for (int j = 0; j < 2; j++) {
                uint32_t b0, b1, b2_, b3;
                ldsm_x4(b0, b1, b2_, b3, bb + boff[j] + ks * 32);
                hmma16816(fr[j * 2 + 0], A, b0, b1);
                hmma16816(fr[j * 2 + 1], A, b2_, b3);
            }
        }
    };

    LDG(0);
    STS(0);
    __syncthreads();
#pragma unroll 1
    for (int s = 0; s < 64; s++) {
        if (s < 63) LDG(s + 1);
        COMP(s & 1);
        if (s < 63) STS((s + 1) & 1);
        if ((s & 3) == 3) {
            float4 cc = WCOEF[s >> 2];
#pragma unroll
            for (int nf = 0; nf < 4; nf++)
#pragma unroll
                for (int ti = 0; ti < 2; ti++)
#pragma unroll
                    for (int cci = 0; cci < 2; cci++) {
                        float m = fr[nf][ti * 2 + cci];
                        O_[ti][nf][cci][0] += cc.x * m;
                        O_[ti][nf][cci][1] += cc.y * m;
                        O_[ti][nf][cci][2] += cc.z * m;
                        O_[ti][nf][cci][3] += cc.w * m;
                    }
#pragma unroll
            for (int n = 0; n < 4; n++)
#pragma unroll
                for (int c = 0; c < 4; c++) fr[n][c] = 0.f;
        }
        __syncthreads();
    }

    // ---------------- epilogue (fragment-direct stores) ----------------
#pragma unroll
    for (int ti = 0; ti < 2; ti++) {
        int tglob = tileb + wm * 16 + g + ti * 8;
        int n = tglob / 784;
        int r = tglob - n * 784;
        int ty = r / 28, tx = r - (r / 28) * 28;
        int y0 = 2 * ty, x0 = 2 * tx;

        if (phase == 1) {
#pragma unroll
            for (int py = 0; py < 2; py++)
#pragma unroll
                for (int px = 0; px < 2; px++) {
                    size_t pix = (size_t)((n * 56 + y0 + py) * 56 + x0 + px) * 256;
#pragma unroll
                    for (int nf = 0; nf < 4; nf++) {
                        int c = cob + wn * 32 + nf * 8 + tig * 2;
                        float v0 = O_[ti][nf][0][py * 2 + px] * (1.f / 9.f) * ivs[c] + bis[c];
                        float v1 = O_[ti][nf][1][py * 2 + px] * (1.f / 9.f) * ivs[c + 1] + bis[c + 1];
                        v0 = fminf(fmaxf(v0, 0.f), 1.f);
                        v1 = fminf(fmaxf(v1, 0.f), 1.f);
                        int q0 = (int)rintf(v0 * 3.f);
                        int q1 = (int)rintf(v1 * 3.f);
                        uchar2 pk;
                        pk.x = (uint8_t)__byte_perm(ACT_E4M3, 0, q0);
                        pk.y = (uint8_t)__byte_perm(ACT_E4M3, 0, q1);
                        *(uchar2*)(g_act1 + pix + c) = pk;
                    }
                }
        } else {
#pragma unroll
            for (int nf = 0; nf < 4; nf++)
#pragma unroll
                for (int cci = 0; cci < 2; cci++) {
                    int c = cob + wn * 32 + nf * 8 + tig * 2 + cci;
                    size_t base = ((size_t)n * 256 + c) * HW;
#pragma unroll
                    for (int py = 0; py < 2; py++) {
                        size_t idx = base + (size_t)(y0 + py) * 56 + x0;
                        out[idx] = O_[ti][nf][cci][py * 2 + 0] * (1.f / 9.f) + xin[idx];
                        out[idx + 1] = O_[ti][nf][cci][py * 2 + 1] * (1.f / 9.f) + xin[idx + 1];
                    }
                }
        }
    }
}

// ---------------- launch ----------------
extern "C" void kernel_launch(void* const* d_in, const int* in_sizes, int n_in,
                              void* d_out, int out_size) {
    const float* x  = (const float*)d_in[0];
    const float* w1 = (const float*)d_in[1];
    const float* w2 = (const float*)d_in[2];
    const float* g1 = (const float*)d_in[3];
    const float* b1 = (const float*)d_in[4];
    const float* m1 = (const float*)d_in[5];
    const float* v1 = (const float*)d_in[6];
    const float* g2 = (const float*)d_in[7];
    const float* b2 = (const float*)d_in[8];
    const float* m2 = (const float*)d_in[9];
    const float* v2 = (const float*)d_in[10];
    float* out = (float*)d_out;
    (void)in_sizes; (void)n_in; (void)out_size;

    cudaFuncSetAttribute(wgemm_kernel,
                         cudaFuncAttributeMaxDynamicSharedMemorySize, WG_SMEM);

    init_kernel<<<1, 1>>>();
    wmax_kernel<<<dim3(128, 2), 256>>>(w1, w2);
    utrans_kernel<<<dim3(256, 2), 256>>>(w1, w2);
    actprep_kernel<<<32 * 56, 256>>>(x, g1, b1, m1, v1);
    vtrans_kernel<<<NTILES / 4, 256>>>(0);
    wgemm_kernel<<<dim3(4, 392), 256, WG_SMEM>>>(1, g2, b2, m2, v2, x, out);
    vtrans_kernel<<<NTILES / 4, 256>>>(1);
    wgemm_kernel<<<dim3(4, 392), 256, WG_SMEM>>>(2, g2, b2, m2, v2, x, out);
}